// round 14
// baseline (speedup 1.0000x reference)
#include <cuda_runtime.h>
#include <float.h>
#include <math.h>

// Problem constants
#define Bc  2
#define Sc  2048
#define Dc  1024
#define Hc  16
#define DKc 64
#define KSEL 32

typedef unsigned long long u64;

// Packed f32x2 helpers (Blackwell FFMA2 path; per-lane IEEE fp32 => bit-exact)
__device__ __forceinline__ u64 fma2(u64 a, u64 b, u64 c) {
    u64 d;
    asm("fma.rn.f32x2 %0, %1, %2, %3;" : "=l"(d) : "l"(a), "l"(b), "l"(c));
    return d;
}
__device__ __forceinline__ u64 add2(u64 a, u64 b) {
    u64 d;
    asm("add.rn.f32x2 %0, %1, %2;" : "=l"(d) : "l"(a), "l"(b));
    return d;
}
__device__ __forceinline__ u64 pack2(float lo, float hi) {
    u64 d;
    asm("mov.b64 %0, {%1, %2};" : "=l"(d) : "f"(lo), "f"(hi));
    return d;
}
__device__ __forceinline__ void unpack2(u64 v, float& lo, float& hi) {
    asm("mov.b64 {%0, %1}, %2;" : "=f"(lo), "=f"(hi) : "l"(v));
}

// Scratch (static device globals — no allocation)
__device__ float g_q[Bc*Hc*Sc*DKc];    // [b][h][s][dk]
__device__ float g_k[Bc*Hc*Sc*DKc];
__device__ float g_v[Bc*Hc*Sc*DKc];
__device__ float g_ctx[Bc*Sc*Dc];      // merged-head [b][s][h*DK+dk]

// ---------------------------------------------------------------------------
// GEMM v3: Y[m, j] = sum_k X[m,k] * W[j,k] + bias[j]
// 128x128 tile, 8x8 microtile via packed f32x2 (rows paired), double-buffered.
// PANELS=1: Eigen-MT aarch64 accumulation (kc=504: panels {504,504,16}) —
//           per-element BIT-EXACT to the R12/R13 passing kernels (Q, K).
// PANELS=0: single ascending chain (V, out-proj; linear error paths).
// MODE 0: flat output; MODE 1: head-split output.
// ---------------------------------------------------------------------------
template<int MODE, int PANELS>
__global__ void __launch_bounds__(256, 1)
gemm_v3(const float* __restrict__ X, const float* __restrict__ W,
        const float* __restrict__ bias, float* __restrict__ Y)
{
    __shared__ float Xs[2][16][132];
    __shared__ float Ws[2][16][132];

    const int tid = threadIdx.x;
    const int m0  = blockIdx.y * 128;
    const int n0  = blockIdx.x * 128;
    const int tx  = tid & 15;          // n microtile
    const int ty  = tid >> 4;          // m microtile
    const int lr  = tid >> 2;          // 0..63 loader row
    const int lc  = (tid & 3) << 2;    // 0,4,8,12 loader k col

    const float* Xp0 = X + (size_t)(m0 + lr) * Dc + lc;
    const float* Xp1 = X + (size_t)(m0 + lr + 64) * Dc + lc;
    const float* Wp0 = W + (size_t)(n0 + lr) * Dc + lc;
    const float* Wp1 = W + (size_t)(n0 + lr + 64) * Dc + lc;

    // Packed accumulators: pan2[i2][j] holds rows pair, lanes = (lo,hi) rows
    u64 pan2[4][8];
    u64 acc2[4][8];
#pragma unroll
    for (int i = 0; i < 4; ++i)
#pragma unroll
        for (int j = 0; j < 8; ++j) { pan2[i][j] = 0ull; if (PANELS) acc2[i][j] = 0ull; }

    // preload tile 0
    float4 xa = *(const float4*)Xp0;
    float4 xb = *(const float4*)Xp1;
    float4 wa = *(const float4*)Wp0;
    float4 wb = *(const float4*)Wp1;
    Xs[0][lc+0][lr] = xa.x; Xs[0][lc+1][lr] = xa.y; Xs[0][lc+2][lr] = xa.z; Xs[0][lc+3][lr] = xa.w;
    Xs[0][lc+0][lr+64] = xb.x; Xs[0][lc+1][lr+64] = xb.y; Xs[0][lc+2][lr+64] = xb.z; Xs[0][lc+3][lr+64] = xb.w;
    Ws[0][lc+0][lr] = wa.x; Ws[0][lc+1][lr] = wa.y; Ws[0][lc+2][lr] = wa.z; Ws[0][lc+3][lr] = wa.w;
    Ws[0][lc+0][lr+64] = wb.x; Ws[0][lc+1][lr+64] = wb.y; Ws[0][lc+2][lr+64] = wb.z; Ws[0][lc+3][lr+64] = wb.w;
    __syncthreads();

    int buf = 0;
    for (int tile = 0; tile < 64; ++tile) {
        const bool haveNext = (tile < 63);
        if (haveNext) {
            const int kn = (tile + 1) * 16;
            xa = *(const float4*)(Xp0 + kn);
            xb = *(const float4*)(Xp1 + kn);
            wa = *(const float4*)(Wp0 + kn);
            wb = *(const float4*)(Wp1 + kn);
        }
        const bool midflush = PANELS && (tile == 31);

#pragma unroll
        for (int k = 0; k < 16; ++k) {
            // row pairs directly from smem (adjacent floats -> one 64-bit reg)
            u64 ap0 = *(const u64*)&Xs[buf][k][ty * 4];        // rows ty*4, +1
            u64 ap1 = *(const u64*)&Xs[buf][k][ty * 4 + 2];    // rows ty*4+2, +3
            u64 ap2 = *(const u64*)&Xs[buf][k][64 + ty * 4];
            u64 ap3 = *(const u64*)&Xs[buf][k][64 + ty * 4 + 2];
            float4 b0 = *(const float4*)&Ws[buf][k][tx * 4];
            float4 b1 = *(const float4*)&Ws[buf][k][64 + tx * 4];
            u64 bd[8];
            bd[0] = pack2(b0.x, b0.x); bd[1] = pack2(b0.y, b0.y);
            bd[2] = pack2(b0.z, b0.z); bd[3] = pack2(b0.w, b0.w);
            bd[4] = pack2(b1.x, b1.x); bd[5] = pack2(b1.y, b1.y);
            bd[6] = pack2(b1.z, b1.z); bd[7] = pack2(b1.w, b1.w);
#pragma unroll
            for (int j = 0; j < 8; ++j) {
                pan2[0][j] = fma2(ap0, bd[j], pan2[0][j]);
                pan2[1][j] = fma2(ap1, bd[j], pan2[1][j]);
                pan2[2][j] = fma2(ap2, bd[j], pan2[2][j]);
                pan2[3][j] = fma2(ap3, bd[j], pan2[3][j]);
            }
            if (PANELS && k == 7 && midflush) {    // k = 504 boundary
#pragma unroll
                for (int i = 0; i < 4; ++i)
#pragma unroll
                    for (int j = 0; j < 8; ++j) {
                        acc2[i][j] = add2(acc2[i][j], pan2[i][j]);
                        pan2[i][j] = 0ull;
                    }
            }
        }
        if (PANELS && (tile == 62 || tile == 63)) {   // k = 1008, 1024
#pragma unroll
            for (int i = 0; i < 4; ++i)
#pragma unroll
                for (int j = 0; j < 8; ++j) {
                    acc2[i][j] = add2(acc2[i][j], pan2[i][j]);
                    pan2[i][j] = 0ull;
                }
        }
        if (haveNext) {
            const int nb = buf ^ 1;
            Xs[nb][lc+0][lr] = xa.x; Xs[nb][lc+1][lr] = xa.y; Xs[nb][lc+2][lr] = xa.z; Xs[nb][lc+3][lr] = xa.w;
            Xs[nb][lc+0][lr+64] = xb.x; Xs[nb][lc+1][lr+64] = xb.y; Xs[nb][lc+2][lr+64] = xb.z; Xs[nb][lc+3][lr+64] = xb.w;
            Ws[nb][lc+0][lr] = wa.x; Ws[nb][lc+1][lr] = wa.y; Ws[nb][lc+2][lr] = wa.z; Ws[nb][lc+3][lr] = wa.w;
            Ws[nb][lc+0][lr+64] = wb.x; Ws[nb][lc+1][lr+64] = wb.y; Ws[nb][lc+2][lr+64] = wb.z; Ws[nb][lc+3][lr+64] = wb.w;
            __syncthreads();
            buf = nb;
        }
    }

    // epilogue: unpack pairs, add bias (same scalar op order as R13)
#pragma unroll
    for (int i2 = 0; i2 < 4; ++i2) {
        const int rbase = (i2 < 2) ? (ty * 4 + i2 * 2) : (64 + ty * 4 + (i2 - 2) * 2);
#pragma unroll
        for (int j = 0; j < 8; ++j) {
            const int c = n0 + ((j < 4) ? (tx * 4 + j) : (64 + tx * 4 + j - 4));
            float lo, hi;
            unpack2(PANELS ? acc2[i2][j] : pan2[i2][j], lo, hi);
            const float r0 = lo + bias[c];
            const float r1 = hi + bias[c];
            const int mA = m0 + rbase;
            const int mB = mA + 1;
            if (MODE == 0) {
                Y[(size_t)mA * Dc + c] = r0;
                Y[(size_t)mB * Dc + c] = r1;
            } else {
                const int hh = c >> 6;
                const int dk = c & 63;
                {
                    const int bb = mA >> 11, s = mA & (Sc - 1);
                    Y[(((size_t)(bb * Hc + hh) * Sc) + s) * DKc + dk] = r0;
                }
                {
                    const int bb = mB >> 11, s = mB & (Sc - 1);
                    Y[(((size_t)(bb * Hc + hh) * Sc) + s) * DKc + dk] = r1;
                }
            }
        }
    }
}

// ---------------------------------------------------------------------------
// Attention v3: per block = 16 query rows of one (b,h).
//   scores: packed f32x2 — each thread's two keys accumulate in one 64-bit
//           register ({s0,s1}); K staged in PAIR layout, q duplicated in smem.
//           Per-lane chain = ascending-d IEEE fp32 fma => bit-exact to R13.
//   top-32 / softmax / ctx: identical to R13.
// 512 threads, ~184 KB dynamic smem.
// ---------------------------------------------------------------------------
#define TQ 16
#define SST 2052     // score row stride (floats)
#define NKT 64       // keys per staged tile
#define KROW 66      // Kp/qdup row stride in u64 (bank-conflict pad)

__global__ void __launch_bounds__(512, 1)
attn_v3(const int* __restrict__ mask, const int* __restrict__ topk_p)
{
    extern __shared__ char smraw[];
    float* qs   = (float*)smraw;                         // 16*64 f
    u64*   qdup = (u64*)(qs + TQ * 64);                  // 16*66 u64
    float* sc   = (float*)(qdup + TQ * KROW);            // 16*2052 f
    u64*   Kp   = (u64*)(sc + TQ * SST);                 // 2*32*66 u64
    float* selv = (float*)(Kp + 2 * 32 * KROW);          // 16*32 f
    float* sele = selv + TQ * KSEL;                      // 16*32 f
    int*   seli = (int*)(sele + TQ * KSEL);              // 16*32 i

    const int tid = threadIdx.x;
    const int bh  = blockIdx.y;
    const int b   = bh >> 4;
    const int h   = bh & 15;
    const int q0  = blockIdx.x * TQ;

    const float* Qb = g_q + ((size_t)bh * Sc + q0) * DKc;
    const float* Kb = g_k + (size_t)bh * Sc * DKc;
    const float* Vb = g_v + (size_t)bh * Sc * DKc;

    // load Q tile; build packed q-duplicates
    for (int i = tid; i < TQ * DKc; i += 512) {
        const float v = Qb[i];
        qs[i] = v;
        qdup[(i >> 6) * KROW + (i & 63)] = pack2(v, v);
    }

    // stage K tile 0 in pair layout: Kp[j2][d] = {K[2j2][d], K[2j2+1][d]}
    const int j2 = tid >> 4;            // 0..31
    const int dc = (tid & 15) * 4;      // 0..60
    {
        const float4 r0 = *(const float4*)(Kb + (size_t)(2 * j2) * DKc + dc);
        const float4 r1 = *(const float4*)(Kb + (size_t)(2 * j2 + 1) * DKc + dc);
        u64* dst = Kp + (size_t)j2 * KROW + dc;
        dst[0] = pack2(r0.x, r1.x); dst[1] = pack2(r0.y, r1.y);
        dst[2] = pack2(r0.z, r1.z); dst[3] = pack2(r0.w, r1.w);
    }
    __syncthreads();

    // ---- scores ----
    {
        const int r   = tid & 15;              // query row
        const int grp = tid >> 4;              // 0..31 -> keys 2g, 2g+1
        const int* mrow = mask + ((size_t)b * Sc + (q0 + r)) * Sc;
        float* srow = sc + r * SST;
        const u64* qd = qdup + r * KROW;

        int buf = 0;
        for (int kt = 0; kt < Sc / NKT; ++kt) {
            float4 pf0, pf1;
            const bool haveNext = (kt + 1 < Sc / NKT);
            if (haveNext) {
                const float* kn = Kb + (size_t)(kt + 1) * NKT * DKc;
                pf0 = *(const float4*)(kn + (size_t)(2 * j2) * DKc + dc);
                pf1 = *(const float4*)(kn + (size_t)(2 * j2 + 1) * DKc + dc);
            }

            const u64* kp = Kp + (size_t)(buf * 32 + grp) * KROW;
            u64 s01 = 0ull;                    // lanes {s0, s1}, ascending d
#pragma unroll
            for (int d = 0; d < 64; d += 2) {
                const ulonglong2 kk = *(const ulonglong2*)&kp[d];
                const ulonglong2 qq = *(const ulonglong2*)&qd[d];
                s01 = fma2(qq.x, kk.x, s01);
                s01 = fma2(qq.y, kk.y, s01);
            }
            float s0, s1;
            unpack2(s01, s0, s1);
            s0 *= 0.125f;                      // /sqrt(64): exact
            s1 *= 0.125f;
            const int j = kt * NKT + grp * 2;
            const int2 mm = *(const int2*)(mrow + j);
            if (mm.x == 0) s0 = -1e9f;
            if (mm.y == 0) s1 = -1e9f;
            srow[j]     = s0;
            srow[j + 1] = s1;

            if (haveNext) {
                u64* dst = Kp + (size_t)((buf ^ 1) * 32 + j2) * KROW + dc;
                dst[0] = pack2(pf0.x, pf1.x); dst[1] = pack2(pf0.y, pf1.y);
                dst[2] = pack2(pf0.z, pf1.z); dst[3] = pack2(pf0.w, pf1.w);
                __syncthreads();
                buf ^= 1;
            }
        }
    }
    __syncthreads();

    int kk = *topk_p;
    if (kk > KSEL) kk = KSEL;

    // ---- top-k: warp w owns query row w; lane caches its own argmax ----
    const int w    = tid >> 5;
    const int lane = tid & 31;
    float* scr = sc + w * SST;

    float lv; int li;
    {
        float nv = -FLT_MAX; int ni = 0x7fffffff;
#pragma unroll
        for (int j = 0; j < 16; ++j) {
            const int base = j * 128 + lane * 4;
            const float4 vv = *(const float4*)&scr[base];
            if (vv.x > nv) { nv = vv.x; ni = base; }
            if (vv.y > nv) { nv = vv.y; ni = base + 1; }
            if (vv.z > nv) { nv = vv.z; ni = base + 2; }
            if (vv.w > nv) { nv = vv.w; ni = base + 3; }
        }
        lv = nv; li = ni;
    }

    for (int sel = 0; sel < kk; ++sel) {
        float bv = lv; int bi = li;
#pragma unroll
        for (int off = 16; off; off >>= 1) {
            const float ov = __shfl_down_sync(0xffffffffu, bv, off);
            const int   oi = __shfl_down_sync(0xffffffffu, bi, off);
            if (ov > bv || (ov == bv && oi < bi)) { bv = ov; bi = oi; }
        }
        bi = __shfl_sync(0xffffffffu, bi, 0);
        bv = __shfl_sync(0xffffffffu, bv, 0);
        if (lane == 0) {
            selv[w * KSEL + sel] = bv;
            seli[w * KSEL + sel] = bi;
        }
        const int owner = (bi >> 2) & 31;
        if (lane == owner) {
            scr[bi] = -FLT_MAX;
            float nv = -FLT_MAX; int ni = 0x7fffffff;
#pragma unroll
            for (int j = 0; j < 16; ++j) {
                const int base = j * 128 + lane * 4;
                const float4 vv = *(const float4*)&scr[base];
                if (vv.x > nv) { nv = vv.x; ni = base; }
                if (vv.y > nv) { nv = vv.y; ni = base + 1; }
                if (vv.z > nv) { nv = vv.z; ni = base + 2; }
                if (vv.w > nv) { nv = vv.w; ni = base + 3; }
            }
            lv = nv; li = ni;
        }
        __syncwarp();
    }

    // ---- softmax over selected (sequential ascending denominator) ----
    const float mx = selv[w * KSEL];
    float e = 0.f;
    if (lane < kk) {
        e = expf(selv[w * KSEL + lane] - mx);
        sele[w * KSEL + lane] = e;
    }
    __syncwarp();
    float ssum = 0.f;
    for (int i = 0; i < kk; ++i)
        ssum += sele[w * KSEL + i];
    const float p = e / ssum;

    // ---- ctx gather (ascending over selections) ----
    const int myi = (lane < kk) ? seli[w * KSEL + lane] : 0;
    float a0 = 0.f, a1 = 0.f;
    for (int sel = 0; sel < kk; ++sel) {
        const float pp = __shfl_sync(0xffffffffu, p, sel);
        const int   id = __shfl_sync(0xffffffffu, myi, sel);
        const float* vp = Vb + (size_t)id * DKc;
        a0 = fmaf(pp, vp[lane],      a0);
        a1 = fmaf(pp, vp[lane + 32], a1);
    }

    float* outp = g_ctx + ((size_t)(b * Sc + q0 + w)) * Dc + h * DKc;
    outp[lane]      = a0;
    outp[lane + 32] = a1;
}

#define SMEM_ATTN (TQ*64*4 + TQ*KROW*8 + TQ*SST*4 + 2*32*KROW*8 + TQ*KSEL*4*2 + TQ*KSEL*4)

// ---------------------------------------------------------------------------
extern "C" void kernel_launch(void* const* d_in, const int* in_sizes, int n_in,
                              void* d_out, int out_size)
{
    const float* query = (const float*)d_in[0];
    const float* key   = (const float*)d_in[1];
    const float* value = (const float*)d_in[2];
    const float* Wq    = (const float*)d_in[3];
    const float* bq    = (const float*)d_in[4];
    const float* Wk    = (const float*)d_in[5];
    const float* bk    = (const float*)d_in[6];
    const float* Wv    = (const float*)d_in[7];
    const float* bv    = (const float*)d_in[8];
    const float* Wo    = (const float*)d_in[9];
    const float* bo    = (const float*)d_in[10];
    const int*   mask  = (const int*)d_in[11];
    const int*   topk  = (const int*)d_in[12];
    float* out = (float*)d_out;

    float *pq, *pk, *pv, *pctx;
    cudaGetSymbolAddress((void**)&pq,   g_q);
    cudaGetSymbolAddress((void**)&pk,   g_k);
    cudaGetSymbolAddress((void**)&pv,   g_v);
    cudaGetSymbolAddress((void**)&pctx, g_ctx);

    cudaFuncSetAttribute(attn_v3,
                         cudaFuncAttributeMaxDynamicSharedMemorySize, SMEM_ATTN);

    dim3 gg(Dc / 128, (Bc * Sc) / 128);   // (8, 32)

    // Q, K: bit-exact Eigen panel accumulation
    gemm_v3<1, 1><<<gg, 256>>>(query, Wq, bq, pq);
    gemm_v3<1, 1><<<gg, 256>>>(key,   Wk, bk, pk);
    // V: linear path — single-chain accumulator
    gemm_v3<1, 0><<<gg, 256>>>(value, Wv, bv, pv);

    attn_v3<<<dim3(Sc / TQ, Bc * Hc), 512, SMEM_ATTN>>>(mask, topk);

    // output projection: linear path
    gemm_v3<0, 0><<<gg, 256>>>(pctx, Wo, bo, out);
}

// round 15
// speedup vs baseline: 1.5925x; 1.5925x over previous
#include <cuda_runtime.h>
#include <float.h>
#include <math.h>

// Problem constants
#define Bc  2
#define Sc  2048
#define Dc  1024
#define Hc  16
#define DKc 64
#define KSEL 32

// Scratch (static device globals — no allocation)
__device__ float g_q[Bc*Hc*Sc*DKc];    // [b][h][s][dk]
__device__ float g_k[Bc*Hc*Sc*DKc];
__device__ float g_v[Bc*Hc*Sc*DKc];
__device__ float g_ctx[Bc*Sc*Dc];      // merged-head [b][s][h*DK+dk]

// Monotone float<->uint bijection: f1 < f2  <=>  mono(f1) < mono(f2) (unsigned)
__device__ __forceinline__ unsigned mono(float f) {
    unsigned u = __float_as_uint(f);
    return (u & 0x80000000u) ? ~u : (u | 0x80000000u);
}
__device__ __forceinline__ float invmono(unsigned m) {
    unsigned u = (m & 0x80000000u) ? (m & 0x7fffffffu) : ~m;
    return __uint_as_float(u);
}

// ---------------------------------------------------------------------------
// GEMM v2 (R13, proven): Y[m, j] = sum_k X[m,k] * W[j,k] + bias[j]
// 128x128 tile, 8x8 microtile, double-buffered smem, 256 threads.
// PANELS=1: Eigen-MT aarch64 accumulation (kc=504: panels {504,504,16}) —
//           BIT-EXACT per element (Q, K).   PANELS=0: single chain (V, out).
// ---------------------------------------------------------------------------
template<int MODE, int PANELS>
__global__ void __launch_bounds__(256, 1)
gemm_v2(const float* __restrict__ X, const float* __restrict__ W,
        const float* __restrict__ bias, float* __restrict__ Y)
{
    __shared__ float Xs[2][16][132];
    __shared__ float Ws[2][16][132];

    const int tid = threadIdx.x;
    const int m0  = blockIdx.y * 128;
    const int n0  = blockIdx.x * 128;
    const int tx  = tid & 15;
    const int ty  = tid >> 4;
    const int lr  = tid >> 2;
    const int lc  = (tid & 3) << 2;

    const float* Xp0 = X + (size_t)(m0 + lr) * Dc + lc;
    const float* Xp1 = X + (size_t)(m0 + lr + 64) * Dc + lc;
    const float* Wp0 = W + (size_t)(n0 + lr) * Dc + lc;
    const float* Wp1 = W + (size_t)(n0 + lr + 64) * Dc + lc;

    float pan[8][8];
    float acc[8][8];
#pragma unroll
    for (int i = 0; i < 8; ++i)
#pragma unroll
        for (int j = 0; j < 8; ++j) { pan[i][j] = 0.f; if (PANELS) acc[i][j] = 0.f; }

    float4 xa = *(const float4*)Xp0;
    float4 xb = *(const float4*)Xp1;
    float4 wa = *(const float4*)Wp0;
    float4 wb = *(const float4*)Wp1;
    Xs[0][lc+0][lr] = xa.x; Xs[0][lc+1][lr] = xa.y; Xs[0][lc+2][lr] = xa.z; Xs[0][lc+3][lr] = xa.w;
    Xs[0][lc+0][lr+64] = xb.x; Xs[0][lc+1][lr+64] = xb.y; Xs[0][lc+2][lr+64] = xb.z; Xs[0][lc+3][lr+64] = xb.w;
    Ws[0][lc+0][lr] = wa.x; Ws[0][lc+1][lr] = wa.y; Ws[0][lc+2][lr] = wa.z; Ws[0][lc+3][lr] = wa.w;
    Ws[0][lc+0][lr+64] = wb.x; Ws[0][lc+1][lr+64] = wb.y; Ws[0][lc+2][lr+64] = wb.z; Ws[0][lc+3][lr+64] = wb.w;
    __syncthreads();

    int buf = 0;
    for (int tile = 0; tile < 64; ++tile) {
        const bool haveNext = (tile < 63);
        if (haveNext) {
            const int kn = (tile + 1) * 16;
            xa = *(const float4*)(Xp0 + kn);
            xb = *(const float4*)(Xp1 + kn);
            wa = *(const float4*)(Wp0 + kn);
            wb = *(const float4*)(Wp1 + kn);
        }
        const bool midflush = PANELS && (tile == 31);

#pragma unroll
        for (int k = 0; k < 16; ++k) {
            float4 a0 = *(const float4*)&Xs[buf][k][ty * 4];
            float4 a1 = *(const float4*)&Xs[buf][k][64 + ty * 4];
            float4 b0 = *(const float4*)&Ws[buf][k][tx * 4];
            float4 b1 = *(const float4*)&Ws[buf][k][64 + tx * 4];
            float av[8] = {a0.x, a0.y, a0.z, a0.w, a1.x, a1.y, a1.z, a1.w};
            float bv[8] = {b0.x, b0.y, b0.z, b0.w, b1.x, b1.y, b1.z, b1.w};
#pragma unroll
            for (int i = 0; i < 8; ++i)
#pragma unroll
                for (int j = 0; j < 8; ++j)
                    pan[i][j] = fmaf(av[i], bv[j], pan[i][j]);
            if (PANELS && k == 7 && midflush) {     // k = 504 boundary
#pragma unroll
                for (int i = 0; i < 8; ++i)
#pragma unroll
                    for (int j = 0; j < 8; ++j) {
                        acc[i][j] += pan[i][j];
                        pan[i][j] = 0.f;
                    }
            }
        }
        if (PANELS && (tile == 62 || tile == 63)) { // k = 1008, 1024
#pragma unroll
            for (int i = 0; i < 8; ++i)
#pragma unroll
                for (int j = 0; j < 8; ++j) {
                    acc[i][j] += pan[i][j];
                    pan[i][j] = 0.f;
                }
        }
        if (haveNext) {
            const int nb = buf ^ 1;
            Xs[nb][lc+0][lr] = xa.x; Xs[nb][lc+1][lr] = xa.y; Xs[nb][lc+2][lr] = xa.z; Xs[nb][lc+3][lr] = xa.w;
            Xs[nb][lc+0][lr+64] = xb.x; Xs[nb][lc+1][lr+64] = xb.y; Xs[nb][lc+2][lr+64] = xb.z; Xs[nb][lc+3][lr+64] = xb.w;
            Ws[nb][lc+0][lr] = wa.x; Ws[nb][lc+1][lr] = wa.y; Ws[nb][lc+2][lr] = wa.z; Ws[nb][lc+3][lr] = wa.w;
            Ws[nb][lc+0][lr+64] = wb.x; Ws[nb][lc+1][lr+64] = wb.y; Ws[nb][lc+2][lr+64] = wb.z; Ws[nb][lc+3][lr+64] = wb.w;
            __syncthreads();
            buf = nb;
        }
    }

#pragma unroll
    for (int i = 0; i < 8; ++i) {
        const int m = m0 + ((i < 4) ? (ty * 4 + i) : (64 + ty * 4 + i - 4));
#pragma unroll
        for (int j = 0; j < 8; ++j) {
            const int c = n0 + ((j < 4) ? (tx * 4 + j) : (64 + tx * 4 + j - 4));
            const float r = (PANELS ? acc[i][j] : pan[i][j]) + bias[c];
            if (MODE == 0) {
                Y[(size_t)m * Dc + c] = r;
            } else {
                const int bb = m >> 11;
                const int s  = m & (Sc - 1);
                const int hh = c >> 6;
                const int dk = c & 63;
                Y[(((size_t)(bb * Hc + hh) * Sc) + s) * DKc + dk] = r;
            }
        }
    }
}

// ---------------------------------------------------------------------------
// Attention v4: scores identical to R13 (bit-exact). Top-k rebuilt:
//   - monotone-uint values => warp argmax via REDUX (__reduce_max_sync)
//   - min-global-index tie-break via __reduce_min_sync over winner lanes
//   - per-lane 4 cached sub-maxima (16 scores each); removal rescans only the
//     affected subgroup. Strict >, ascending scans => identical selection
//     order to lax.top_k.
// ---------------------------------------------------------------------------
#define TQ 16
#define SST 2052     // score row stride (floats)
#define NKT 64       // keys per staged tile

// Recompute submax over subgroup g (16 floats), ascending index, strict >.
#define SUBMAX(g, outm, outi)                                              \
    {                                                                      \
        float nv = -FLT_MAX; int ni = 0x7fffffff;                          \
        _Pragma("unroll")                                                  \
        for (int jj = 0; jj < 4; ++jj) {                                   \
            const int base = ((g) * 4 + jj) * 128 + lane * 4;              \
            const float4 vv = *(const float4*)&scr[base];                  \
            if (vv.x > nv) { nv = vv.x; ni = base; }                       \
            if (vv.y > nv) { nv = vv.y; ni = base + 1; }                   \
            if (vv.z > nv) { nv = vv.z; ni = base + 2; }                   \
            if (vv.w > nv) { nv = vv.w; ni = base + 3; }                   \
        }                                                                  \
        outm = mono(nv); outi = ni;                                        \
    }

__global__ void __launch_bounds__(512, 1)
attn_v4(const int* __restrict__ mask, const int* __restrict__ topk_p)
{
    extern __shared__ float sm[];
    float* qs   = sm;                          // 16*64
    float* sc   = qs + TQ * 64;                // 16*2052
    float* Ks   = sc + TQ * SST;               // 2 * 64*64
    float* selv = Ks + 2 * NKT * DKc;          // 16*32
    float* sele = selv + TQ * KSEL;            // 16*32
    int*   seli = (int*)(sele + TQ * KSEL);    // 16*32

    const int tid = threadIdx.x;
    const int bh  = blockIdx.y;
    const int b   = bh >> 4;
    const int h   = bh & 15;
    const int q0  = blockIdx.x * TQ;

    const float* Qb = g_q + ((size_t)bh * Sc + q0) * DKc;
    const float* Kb = g_k + (size_t)bh * Sc * DKc;
    const float* Vb = g_v + (size_t)bh * Sc * DKc;

    // load Q tile + K tile 0
    for (int i = tid; i < TQ * DKc; i += 512) qs[i] = Qb[i];
    {
        const float4* src = (const float4*)Kb;
        float4* dst = (float4*)Ks;
        dst[tid]       = src[tid];
        dst[tid + 512] = src[tid + 512];
    }
    __syncthreads();

    // ---- scores (bit-exact: single ascending fma chain per score) ----
    {
        const int r   = tid & 15;
        const int grp = tid >> 4;
        const int* mrow = mask + ((size_t)b * Sc + (q0 + r)) * Sc;
        float* srow = sc + r * SST;

        float4 qv[16];
#pragma unroll
        for (int d = 0; d < 16; ++d)
            qv[d] = *(const float4*)(qs + r * DKc + d * 4);

        int buf = 0;
        for (int kt = 0; kt < Sc / NKT; ++kt) {
            float4 pf0, pf1;
            const bool haveNext = (kt + 1 < Sc / NKT);
            if (haveNext) {
                const float4* src = (const float4*)(Kb + (size_t)(kt + 1) * NKT * DKc);
                pf0 = src[tid];
                pf1 = src[tid + 512];
            }

            const int jl = grp * 2;
            const float4* k0p = (const float4*)(Ks + (size_t)buf * NKT * DKc + (size_t)jl * DKc);
            const float4* k1p = k0p + 16;
            float s0 = 0.f, s1 = 0.f;
#pragma unroll
            for (int d = 0; d < 16; ++d) {
                float4 k0 = k0p[d];
                float4 k1 = k1p[d];
                s0 = fmaf(qv[d].x, k0.x, s0);
                s0 = fmaf(qv[d].y, k0.y, s0);
                s0 = fmaf(qv[d].z, k0.z, s0);
                s0 = fmaf(qv[d].w, k0.w, s0);
                s1 = fmaf(qv[d].x, k1.x, s1);
                s1 = fmaf(qv[d].y, k1.y, s1);
                s1 = fmaf(qv[d].z, k1.z, s1);
                s1 = fmaf(qv[d].w, k1.w, s1);
            }
            s0 *= 0.125f;
            s1 *= 0.125f;
            const int j = kt * NKT + jl;
            const int2 mm = *(const int2*)(mrow + j);
            if (mm.x == 0) s0 = -1e9f;
            if (mm.y == 0) s1 = -1e9f;
            srow[j]     = s0;
            srow[j + 1] = s1;

            if (haveNext) {
                float4* dst = (float4*)(Ks + (size_t)(buf ^ 1) * NKT * DKc);
                dst[tid]       = pf0;
                dst[tid + 512] = pf1;
                __syncthreads();
                buf ^= 1;
            }
        }
    }
    __syncthreads();

    int kk = *topk_p;
    if (kk > KSEL) kk = KSEL;

    // ---- top-k: warp w owns query row w ----
    const int w    = tid >> 5;
    const int lane = tid & 31;
    float* scr = sc + w * SST;

    // per-lane cached sub-maxima (mono value, index), subgroups of 16 scores
    unsigned sm0, sm1, sm2, sm3;
    int      si0, si1, si2, si3;
    SUBMAX(0, sm0, si0);
    SUBMAX(1, sm1, si1);
    SUBMAX(2, sm2, si2);
    SUBMAX(3, sm3, si3);

    unsigned lvm; int li;   // lane max (mono, idx), ties -> lowest idx
    {
        lvm = sm0; li = si0;
        if (sm1 > lvm) { lvm = sm1; li = si1; }
        if (sm2 > lvm) { lvm = sm2; li = si2; }
        if (sm3 > lvm) { lvm = sm3; li = si3; }
    }

    for (int sel = 0; sel < kk; ++sel) {
        const unsigned m = __reduce_max_sync(0xffffffffu, lvm);
        const int cand = (lvm == m) ? li : 0x7fffffff;
        const int mi = __reduce_min_sync(0xffffffffu, cand);

        if (lane == 0) {
            selv[w * KSEL + sel] = invmono(m);
            seli[w * KSEL + sel] = mi;
        }

        const int owner = (mi >> 2) & 31;        // idx = j*128 + lane*4 + t
        if (lane == owner) {
            scr[mi] = -FLT_MAX;
            const int g = mi >> 9;               // subgroup = (idx/128)/4
            switch (g) {
                case 0: SUBMAX(0, sm0, si0); break;
                case 1: SUBMAX(1, sm1, si1); break;
                case 2: SUBMAX(2, sm2, si2); break;
                default: SUBMAX(3, sm3, si3); break;
            }
            lvm = sm0; li = si0;
            if (sm1 > lvm) { lvm = sm1; li = si1; }
            if (sm2 > lvm) { lvm = sm2; li = si2; }
            if (sm3 > lvm) { lvm = sm3; li = si3; }
        }
    }

    // ---- softmax over selected (sequential ascending denominator) ----
    const float mx = selv[w * KSEL];             // first pick == row max
    float e = 0.f;
    if (lane < kk) {
        e = expf(selv[w * KSEL + lane] - mx);
        sele[w * KSEL + lane] = e;
    }
    __syncwarp();
    float ssum = 0.f;
    for (int i = 0; i < kk; ++i)                 // strictly ascending
        ssum += sele[w * KSEL + i];
    const float p = e / ssum;

    // ---- ctx gather (ascending over selections) ----
    const int myi = (lane < kk) ? seli[w * KSEL + lane] : 0;
    float a0 = 0.f, a1 = 0.f;
    for (int sel = 0; sel < kk; ++sel) {
        const float pp = __shfl_sync(0xffffffffu, p, sel);
        const int   id = __shfl_sync(0xffffffffu, myi, sel);
        const float* vp = Vb + (size_t)id * DKc;
        a0 = fmaf(pp, vp[lane],      a0);
        a1 = fmaf(pp, vp[lane + 32], a1);
    }

    float* outp = g_ctx + ((size_t)(b * Sc + q0 + w)) * Dc + h * DKc;
    outp[lane]      = a0;
    outp[lane + 32] = a1;
}

#define SMEM_ATTN ((TQ*64 + TQ*SST + 2*NKT*DKc + TQ*KSEL*2) * 4 + TQ*KSEL * 4)

// ---------------------------------------------------------------------------
extern "C" void kernel_launch(void* const* d_in, const int* in_sizes, int n_in,
                              void* d_out, int out_size)
{
    const float* query = (const float*)d_in[0];
    const float* key   = (const float*)d_in[1];
    const float* value = (const float*)d_in[2];
    const float* Wq    = (const float*)d_in[3];
    const float* bq    = (const float*)d_in[4];
    const float* Wk    = (const float*)d_in[5];
    const float* bk    = (const float*)d_in[6];
    const float* Wv    = (const float*)d_in[7];
    const float* bv    = (const float*)d_in[8];
    const float* Wo    = (const float*)d_in[9];
    const float* bo    = (const float*)d_in[10];
    const int*   mask  = (const int*)d_in[11];
    const int*   topk  = (const int*)d_in[12];
    float* out = (float*)d_out;

    float *pq, *pk, *pv, *pctx;
    cudaGetSymbolAddress((void**)&pq,   g_q);
    cudaGetSymbolAddress((void**)&pk,   g_k);
    cudaGetSymbolAddress((void**)&pv,   g_v);
    cudaGetSymbolAddress((void**)&pctx, g_ctx);

    cudaFuncSetAttribute(attn_v4,
                         cudaFuncAttributeMaxDynamicSharedMemorySize, SMEM_ATTN);

    dim3 gg(Dc / 128, (Bc * Sc) / 128);   // (8, 32)

    // Q, K: bit-exact Eigen panel accumulation
    gemm_v2<1, 1><<<gg, 256>>>(query, Wq, bq, pq);
    gemm_v2<1, 1><<<gg, 256>>>(key,   Wk, bk, pk);
    // V: linear path — single-chain accumulator
    gemm_v2<1, 0><<<gg, 256>>>(value, Wv, bv, pv);

    attn_v4<<<dim3(Sc / TQ, Bc * Hc), 512, SMEM_ATTN>>>(mask, topk);

    // output projection: linear path
    gemm_v2<0, 0><<<gg, 256>>>(pctx, Wo, bo, out);
}

// round 16
// speedup vs baseline: 1.5933x; 1.0005x over previous
#include <cuda_runtime.h>
#include <float.h>
#include <math.h>

// Problem constants
#define Bc  2
#define Sc  2048
#define Dc  1024
#define Hc  16
#define DKc 64
#define KSEL 32

// Scratch (static device globals — no allocation)
__device__ float g_q[Bc*Hc*Sc*DKc];    // [b][h][s][dk]
__device__ float g_k[Bc*Hc*Sc*DKc];
__device__ float g_v[Bc*Hc*Sc*DKc];
__device__ float g_ctx[Bc*Sc*Dc];      // merged-head [b][s][h*DK+dk]

// Monotone float<->uint bijection: f1 < f2  <=>  mono(f1) < mono(f2) (unsigned)
__device__ __forceinline__ unsigned mono(float f) {
    unsigned u = __float_as_uint(f);
    return (u & 0x80000000u) ? ~u : (u | 0x80000000u);
}
__device__ __forceinline__ float invmono(unsigned m) {
    unsigned u = (m & 0x80000000u) ? (m & 0x7fffffffu) : ~m;
    return __uint_as_float(u);
}

// ---------------------------------------------------------------------------
// GEMM v2 (R13, proven): Y[m, j] = sum_k X[m,k] * W[j,k] + bias[j]
// 128x128 tile, 8x8 microtile, double-buffered smem, 256 threads.
// PANELS=1: Eigen-MT aarch64 accumulation (kc=504: panels {504,504,16}) —
//           BIT-EXACT per element (Q, K).   PANELS=0: single chain (V, out).
// ---------------------------------------------------------------------------
template<int MODE, int PANELS>
__global__ void __launch_bounds__(256, 1)
gemm_v2(const float* __restrict__ X, const float* __restrict__ W,
        const float* __restrict__ bias, float* __restrict__ Y)
{
    __shared__ float Xs[2][16][132];
    __shared__ float Ws[2][16][132];

    const int tid = threadIdx.x;
    const int m0  = blockIdx.y * 128;
    const int n0  = blockIdx.x * 128;
    const int tx  = tid & 15;
    const int ty  = tid >> 4;
    const int lr  = tid >> 2;
    const int lc  = (tid & 3) << 2;

    const float* Xp0 = X + (size_t)(m0 + lr) * Dc + lc;
    const float* Xp1 = X + (size_t)(m0 + lr + 64) * Dc + lc;
    const float* Wp0 = W + (size_t)(n0 + lr) * Dc + lc;
    const float* Wp1 = W + (size_t)(n0 + lr + 64) * Dc + lc;

    float pan[8][8];
    float acc[8][8];
#pragma unroll
    for (int i = 0; i < 8; ++i)
#pragma unroll
        for (int j = 0; j < 8; ++j) { pan[i][j] = 0.f; if (PANELS) acc[i][j] = 0.f; }

    float4 xa = *(const float4*)Xp0;
    float4 xb = *(const float4*)Xp1;
    float4 wa = *(const float4*)Wp0;
    float4 wb = *(const float4*)Wp1;
    Xs[0][lc+0][lr] = xa.x; Xs[0][lc+1][lr] = xa.y; Xs[0][lc+2][lr] = xa.z; Xs[0][lc+3][lr] = xa.w;
    Xs[0][lc+0][lr+64] = xb.x; Xs[0][lc+1][lr+64] = xb.y; Xs[0][lc+2][lr+64] = xb.z; Xs[0][lc+3][lr+64] = xb.w;
    Ws[0][lc+0][lr] = wa.x; Ws[0][lc+1][lr] = wa.y; Ws[0][lc+2][lr] = wa.z; Ws[0][lc+3][lr] = wa.w;
    Ws[0][lc+0][lr+64] = wb.x; Ws[0][lc+1][lr+64] = wb.y; Ws[0][lc+2][lr+64] = wb.z; Ws[0][lc+3][lr+64] = wb.w;
    __syncthreads();

    int buf = 0;
    for (int tile = 0; tile < 64; ++tile) {
        const bool haveNext = (tile < 63);
        if (haveNext) {
            const int kn = (tile + 1) * 16;
            xa = *(const float4*)(Xp0 + kn);
            xb = *(const float4*)(Xp1 + kn);
            wa = *(const float4*)(Wp0 + kn);
            wb = *(const float4*)(Wp1 + kn);
        }
        const bool midflush = PANELS && (tile == 31);

#pragma unroll
        for (int k = 0; k < 16; ++k) {
            float4 a0 = *(const float4*)&Xs[buf][k][ty * 4];
            float4 a1 = *(const float4*)&Xs[buf][k][64 + ty * 4];
            float4 b0 = *(const float4*)&Ws[buf][k][tx * 4];
            float4 b1 = *(const float4*)&Ws[buf][k][64 + tx * 4];
            float av[8] = {a0.x, a0.y, a0.z, a0.w, a1.x, a1.y, a1.z, a1.w};
            float bv[8] = {b0.x, b0.y, b0.z, b0.w, b1.x, b1.y, b1.z, b1.w};
#pragma unroll
            for (int i = 0; i < 8; ++i)
#pragma unroll
                for (int j = 0; j < 8; ++j)
                    pan[i][j] = fmaf(av[i], bv[j], pan[i][j]);
            if (PANELS && k == 7 && midflush) {     // k = 504 boundary
#pragma unroll
                for (int i = 0; i < 8; ++i)
#pragma unroll
                    for (int j = 0; j < 8; ++j) {
                        acc[i][j] += pan[i][j];
                        pan[i][j] = 0.f;
                    }
            }
        }
        if (PANELS && (tile == 62 || tile == 63)) { // k = 1008, 1024
#pragma unroll
            for (int i = 0; i < 8; ++i)
#pragma unroll
                for (int j = 0; j < 8; ++j) {
                    acc[i][j] += pan[i][j];
                    pan[i][j] = 0.f;
                }
        }
        if (haveNext) {
            const int nb = buf ^ 1;
            Xs[nb][lc+0][lr] = xa.x; Xs[nb][lc+1][lr] = xa.y; Xs[nb][lc+2][lr] = xa.z; Xs[nb][lc+3][lr] = xa.w;
            Xs[nb][lc+0][lr+64] = xb.x; Xs[nb][lc+1][lr+64] = xb.y; Xs[nb][lc+2][lr+64] = xb.z; Xs[nb][lc+3][lr+64] = xb.w;
            Ws[nb][lc+0][lr] = wa.x; Ws[nb][lc+1][lr] = wa.y; Ws[nb][lc+2][lr] = wa.z; Ws[nb][lc+3][lr] = wa.w;
            Ws[nb][lc+0][lr+64] = wb.x; Ws[nb][lc+1][lr+64] = wb.y; Ws[nb][lc+2][lr+64] = wb.z; Ws[nb][lc+3][lr+64] = wb.w;
            __syncthreads();
            buf = nb;
        }
    }

#pragma unroll
    for (int i = 0; i < 8; ++i) {
        const int m = m0 + ((i < 4) ? (ty * 4 + i) : (64 + ty * 4 + i - 4));
#pragma unroll
        for (int j = 0; j < 8; ++j) {
            const int c = n0 + ((j < 4) ? (tx * 4 + j) : (64 + tx * 4 + j - 4));
            const float r = (PANELS ? acc[i][j] : pan[i][j]) + bias[c];
            if (MODE == 0) {
                Y[(size_t)m * Dc + c] = r;
            } else {
                const int bb = m >> 11;
                const int s  = m & (Sc - 1);
                const int hh = c >> 6;
                const int dk = c & 63;
                Y[(((size_t)(bb * Hc + hh) * Sc) + s) * DKc + dk] = r;
            }
        }
    }
}

// ---------------------------------------------------------------------------
// Attention v5: scores bit-exact (single ascending fma chain / score).
//   - NKT=128 staged keys per sync (15 syncs instead of 31), two half-tiles
//   - mask loads hoisted to tile start
//   - top-k via REDUX + cached sub-maxima (R15, proven)
//   - kk==32 fast path: fully unrolled softmax + ctx (batched LDGs)
// ---------------------------------------------------------------------------
#define TQ 16
#define SST 2052     // score row stride (floats)
#define NKT 128      // keys per staged tile (two 64-key halves)

// Recompute submax over subgroup g (16 floats), ascending index, strict >.
#define SUBMAX(g, outm, outi)                                              \
    {                                                                      \
        float nv = -FLT_MAX; int ni = 0x7fffffff;                          \
        _Pragma("unroll")                                                  \
        for (int jj = 0; jj < 4; ++jj) {                                   \
            const int base = ((g) * 4 + jj) * 128 + lane * 4;              \
            const float4 vv = *(const float4*)&scr[base];                  \
            if (vv.x > nv) { nv = vv.x; ni = base; }                       \
            if (vv.y > nv) { nv = vv.y; ni = base + 1; }                   \
            if (vv.z > nv) { nv = vv.z; ni = base + 2; }                   \
            if (vv.w > nv) { nv = vv.w; ni = base + 3; }                   \
        }                                                                  \
        outm = mono(nv); outi = ni;                                        \
    }

// One 64-key half-tile of scores for this thread (keys jl, jl+1 of the half).
#define SCORE_PAIR(kbase, mm, jout)                                        \
    {                                                                      \
        const float4* k0p = (const float4*)(Ks + (kbase));                 \
        const float4* k1p = k0p + 16;                                      \
        float s0 = 0.f, s1 = 0.f;                                          \
        _Pragma("unroll")                                                  \
        for (int d = 0; d < 16; ++d) {                                     \
            float4 k0 = k0p[d];                                            \
            float4 k1 = k1p[d];                                            \
            s0 = fmaf(qv[d].x, k0.x, s0);                                  \
            s0 = fmaf(qv[d].y, k0.y, s0);                                  \
            s0 = fmaf(qv[d].z, k0.z, s0);                                  \
            s0 = fmaf(qv[d].w, k0.w, s0);                                  \
            s1 = fmaf(qv[d].x, k1.x, s1);                                  \
            s1 = fmaf(qv[d].y, k1.y, s1);                                  \
            s1 = fmaf(qv[d].z, k1.z, s1);                                  \
            s1 = fmaf(qv[d].w, k1.w, s1);                                  \
        }                                                                  \
        s0 *= 0.125f;                                                      \
        s1 *= 0.125f;                                                      \
        if ((mm).x == 0) s0 = -1e9f;                                       \
        if ((mm).y == 0) s1 = -1e9f;                                       \
        srow[(jout)]     = s0;                                             \
        srow[(jout) + 1] = s1;                                             \
    }

__global__ void __launch_bounds__(512, 1)
attn_v5(const int* __restrict__ mask, const int* __restrict__ topk_p)
{
    extern __shared__ float sm[];
    float* qs   = sm;                          // 16*64
    float* sc   = qs + TQ * 64;                // 16*2052
    float* Ks   = sc + TQ * SST;               // 2 * 128*64
    float* selv = Ks + 2 * NKT * DKc;          // 16*32
    float* sele = selv + TQ * KSEL;            // 16*32
    int*   seli = (int*)(sele + TQ * KSEL);    // 16*32

    const int tid = threadIdx.x;
    const int bh  = blockIdx.y;
    const int b   = bh >> 4;
    const int h   = bh & 15;
    const int q0  = blockIdx.x * TQ;

    const float* Qb = g_q + ((size_t)bh * Sc + q0) * DKc;
    const float* Kb = g_k + (size_t)bh * Sc * DKc;
    const float* Vb = g_v + (size_t)bh * Sc * DKc;

    // load Q tile + K tile 0 (128 keys = 2048 float4, 4 per thread)
    for (int i = tid; i < TQ * DKc; i += 512) qs[i] = Qb[i];
    {
        const float4* src = (const float4*)Kb;
        float4* dst = (float4*)Ks;
        dst[tid]        = src[tid];
        dst[tid + 512]  = src[tid + 512];
        dst[tid + 1024] = src[tid + 1024];
        dst[tid + 1536] = src[tid + 1536];
    }
    __syncthreads();

    // ---- scores ----
    {
        const int r   = tid & 15;
        const int grp = tid >> 4;              // 0..31
        const int jl  = grp * 2;
        const int* mrow = mask + ((size_t)b * Sc + (q0 + r)) * Sc;
        float* srow = sc + r * SST;

        float4 qv[16];
#pragma unroll
        for (int d = 0; d < 16; ++d)
            qv[d] = *(const float4*)(qs + r * DKc + d * 4);

        int buf = 0;
        for (int kt = 0; kt < Sc / NKT; ++kt) {
            const bool haveNext = (kt + 1 < Sc / NKT);
            const int jt = kt * NKT + jl;

            // hoisted mask loads for both halves
            const int2 mmA = *(const int2*)(mrow + jt);
            const int2 mmB = *(const int2*)(mrow + jt + 64);

            // prefetch first half of next tile
            float4 pf0, pf1;
            const float4* nsrc = (const float4*)(Kb + (size_t)(kt + 1) * NKT * DKc);
            if (haveNext) {
                pf0 = nsrc[tid];
                pf1 = nsrc[tid + 512];
            }

            // half 0
            SCORE_PAIR((size_t)buf * NKT * DKc + (size_t)jl * DKc, mmA, jt);

            float4 pf2, pf3;
            if (haveNext) {
                // store first prefetch pair into the other buffer (not read
                // until after the sync), then fetch the second pair
                float4* dst = (float4*)(Ks + (size_t)(buf ^ 1) * NKT * DKc);
                dst[tid]       = pf0;
                dst[tid + 512] = pf1;
                pf2 = nsrc[tid + 1024];
                pf3 = nsrc[tid + 1536];
            }

            // half 1
            SCORE_PAIR((size_t)buf * NKT * DKc + (size_t)(64 + jl) * DKc, mmB, jt + 64);

            if (haveNext) {
                float4* dst = (float4*)(Ks + (size_t)(buf ^ 1) * NKT * DKc);
                dst[tid + 1024] = pf2;
                dst[tid + 1536] = pf3;
                __syncthreads();
                buf ^= 1;
            }
        }
    }
    __syncthreads();

    int kk = *topk_p;
    if (kk > KSEL) kk = KSEL;

    // ---- top-k: warp w owns query row w (REDUX + cached sub-maxima) ----
    const int w    = tid >> 5;
    const int lane = tid & 31;
    float* scr = sc + w * SST;

    unsigned sm0, sm1, sm2, sm3;
    int      si0, si1, si2, si3;
    SUBMAX(0, sm0, si0);
    SUBMAX(1, sm1, si1);
    SUBMAX(2, sm2, si2);
    SUBMAX(3, sm3, si3);

    unsigned lvm; int li;
    {
        lvm = sm0; li = si0;
        if (sm1 > lvm) { lvm = sm1; li = si1; }
        if (sm2 > lvm) { lvm = sm2; li = si2; }
        if (sm3 > lvm) { lvm = sm3; li = si3; }
    }

    for (int sel = 0; sel < kk; ++sel) {
        const unsigned m = __reduce_max_sync(0xffffffffu, lvm);
        const int cand = (lvm == m) ? li : 0x7fffffff;
        const int mi = __reduce_min_sync(0xffffffffu, cand);

        if (lane == 0) {
            selv[w * KSEL + sel] = invmono(m);
            seli[w * KSEL + sel] = mi;
        }

        const int owner = (mi >> 2) & 31;
        if (lane == owner) {
            scr[mi] = -FLT_MAX;
            const int g = mi >> 9;
            switch (g) {
                case 0: SUBMAX(0, sm0, si0); break;
                case 1: SUBMAX(1, sm1, si1); break;
                case 2: SUBMAX(2, sm2, si2); break;
                default: SUBMAX(3, sm3, si3); break;
            }
            lvm = sm0; li = si0;
            if (sm1 > lvm) { lvm = sm1; li = si1; }
            if (sm2 > lvm) { lvm = sm2; li = si2; }
            if (sm3 > lvm) { lvm = sm3; li = si3; }
        }
    }

    // ---- softmax + ctx ----
    float* outp = g_ctx + ((size_t)(b * Sc + q0 + w)) * Dc + h * DKc;
    const float mx = selv[w * KSEL];             // first pick == row max

    if (kk == KSEL) {
        // fast path: fully unrolled (same FP order as dynamic path)
        const float e = expf(selv[w * KSEL + lane] - mx);
        sele[w * KSEL + lane] = e;
        __syncwarp();
        float ssum = 0.f;
#pragma unroll
        for (int i = 0; i < KSEL; ++i)           // strictly ascending
            ssum += sele[w * KSEL + i];
        const float p = e / ssum;

        const int myi = seli[w * KSEL + lane];
        float a0 = 0.f, a1 = 0.f;
#pragma unroll
        for (int sel = 0; sel < KSEL; ++sel) {   // ascending: bit-exact
            const float pp = __shfl_sync(0xffffffffu, p, sel);
            const int   id = __shfl_sync(0xffffffffu, myi, sel);
            const float* vp = Vb + (size_t)id * DKc;
            a0 = fmaf(pp, vp[lane],      a0);
            a1 = fmaf(pp, vp[lane + 32], a1);
        }
        outp[lane]      = a0;
        outp[lane + 32] = a1;
    } else {
        float e = 0.f;
        if (lane < kk) {
            e = expf(selv[w * KSEL + lane] - mx);
            sele[w * KSEL + lane] = e;
        }
        __syncwarp();
        float ssum = 0.f;
        for (int i = 0; i < kk; ++i)
            ssum += sele[w * KSEL + i];
        const float p = e / ssum;

        const int myi = (lane < kk) ? seli[w * KSEL + lane] : 0;
        float a0 = 0.f, a1 = 0.f;
        for (int sel = 0; sel < kk; ++sel) {
            const float pp = __shfl_sync(0xffffffffu, p, sel);
            const int   id = __shfl_sync(0xffffffffu, myi, sel);
            const float* vp = Vb + (size_t)id * DKc;
            a0 = fmaf(pp, vp[lane],      a0);
            a1 = fmaf(pp, vp[lane + 32], a1);
        }
        outp[lane]      = a0;
        outp[lane + 32] = a1;
    }
}

#define SMEM_ATTN ((TQ*64 + TQ*SST + 2*NKT*DKc + TQ*KSEL*2) * 4 + TQ*KSEL * 4)

// ---------------------------------------------------------------------------
extern "C" void kernel_launch(void* const* d_in, const int* in_sizes, int n_in,
                              void* d_out, int out_size)
{
    const float* query = (const float*)d_in[0];
    const float* key   = (const float*)d_in[1];
    const float* value = (const float*)d_in[2];
    const float* Wq    = (const float*)d_in[3];
    const float* bq    = (const float*)d_in[4];
    const float* Wk    = (const float*)d_in[5];
    const float* bk    = (const float*)d_in[6];
    const float* Wv    = (const float*)d_in[7];
    const float* bv    = (const float*)d_in[8];
    const float* Wo    = (const float*)d_in[9];
    const float* bo    = (const float*)d_in[10];
    const int*   mask  = (const int*)d_in[11];
    const int*   topk  = (const int*)d_in[12];
    float* out = (float*)d_out;

    float *pq, *pk, *pv, *pctx;
    cudaGetSymbolAddress((void**)&pq,   g_q);
    cudaGetSymbolAddress((void**)&pk,   g_k);
    cudaGetSymbolAddress((void**)&pv,   g_v);
    cudaGetSymbolAddress((void**)&pctx, g_ctx);

    cudaFuncSetAttribute(attn_v5,
                         cudaFuncAttributeMaxDynamicSharedMemorySize, SMEM_ATTN);

    dim3 gg(Dc / 128, (Bc * Sc) / 128);   // (8, 32)

    // Q, K: bit-exact Eigen panel accumulation
    gemm_v2<1, 1><<<gg, 256>>>(query, Wq, bq, pq);
    gemm_v2<1, 1><<<gg, 256>>>(key,   Wk, bk, pk);
    // V: linear path — single-chain accumulator
    gemm_v2<1, 0><<<gg, 256>>>(value, Wv, bv, pv);

    attn_v5<<<dim3(Sc / TQ, Bc * Hc), 512, SMEM_ATTN>>>(mask, topk);

    // output projection: linear path
    gemm_v2<0, 0><<<gg, 256>>>(pctx, Wo, bo, out);
}

// round 17
// speedup vs baseline: 1.6699x; 1.0481x over previous
#include <cuda_runtime.h>
#include <float.h>
#include <math.h>

// Problem constants
#define Bc  2
#define Sc  2048
#define Dc  1024
#define Hc  16
#define DKc 64
#define KSEL 32

// Scratch (static device globals — no allocation)
__device__ float g_q[Bc*Hc*Sc*DKc];    // [b][h][s][dk]
__device__ float g_k[Bc*Hc*Sc*DKc];
__device__ float g_v[Bc*Hc*Sc*DKc];
__device__ float g_ctx[Bc*Sc*Dc];      // merged-head [b][s][h*DK+dk]

// Monotone float<->uint bijection: f1 < f2  <=>  mono(f1) < mono(f2) (unsigned)
__device__ __forceinline__ unsigned mono(float f) {
    unsigned u = __float_as_uint(f);
    return (u & 0x80000000u) ? ~u : (u | 0x80000000u);
}
__device__ __forceinline__ float invmono(unsigned m) {
    unsigned u = (m & 0x80000000u) ? (m & 0x7fffffffu) : ~m;
    return __uint_as_float(u);
}

// ---------------------------------------------------------------------------
// GEMM v2 (R13, proven): Y[m, j] = sum_k X[m,k] * W[j,k] + bias[j]
// 128x128 tile, 8x8 microtile, double-buffered smem, 256 threads.
// PANELS=1: Eigen-MT aarch64 accumulation (kc=504: panels {504,504,16}) —
//           BIT-EXACT per element (Q, K).   PANELS=0: single chain (V, out).
// ---------------------------------------------------------------------------
template<int MODE, int PANELS>
__global__ void __launch_bounds__(256, 1)
gemm_v2(const float* __restrict__ X, const float* __restrict__ W,
        const float* __restrict__ bias, float* __restrict__ Y)
{
    __shared__ float Xs[2][16][132];
    __shared__ float Ws[2][16][132];

    const int tid = threadIdx.x;
    const int m0  = blockIdx.y * 128;
    const int n0  = blockIdx.x * 128;
    const int tx  = tid & 15;
    const int ty  = tid >> 4;
    const int lr  = tid >> 2;
    const int lc  = (tid & 3) << 2;

    const float* Xp0 = X + (size_t)(m0 + lr) * Dc + lc;
    const float* Xp1 = X + (size_t)(m0 + lr + 64) * Dc + lc;
    const float* Wp0 = W + (size_t)(n0 + lr) * Dc + lc;
    const float* Wp1 = W + (size_t)(n0 + lr + 64) * Dc + lc;

    float pan[8][8];
    float acc[8][8];
#pragma unroll
    for (int i = 0; i < 8; ++i)
#pragma unroll
        for (int j = 0; j < 8; ++j) { pan[i][j] = 0.f; if (PANELS) acc[i][j] = 0.f; }

    float4 xa = *(const float4*)Xp0;
    float4 xb = *(const float4*)Xp1;
    float4 wa = *(const float4*)Wp0;
    float4 wb = *(const float4*)Wp1;
    Xs[0][lc+0][lr] = xa.x; Xs[0][lc+1][lr] = xa.y; Xs[0][lc+2][lr] = xa.z; Xs[0][lc+3][lr] = xa.w;
    Xs[0][lc+0][lr+64] = xb.x; Xs[0][lc+1][lr+64] = xb.y; Xs[0][lc+2][lr+64] = xb.z; Xs[0][lc+3][lr+64] = xb.w;
    Ws[0][lc+0][lr] = wa.x; Ws[0][lc+1][lr] = wa.y; Ws[0][lc+2][lr] = wa.z; Ws[0][lc+3][lr] = wa.w;
    Ws[0][lc+0][lr+64] = wb.x; Ws[0][lc+1][lr+64] = wb.y; Ws[0][lc+2][lr+64] = wb.z; Ws[0][lc+3][lr+64] = wb.w;
    __syncthreads();

    int buf = 0;
    for (int tile = 0; tile < 64; ++tile) {
        const bool haveNext = (tile < 63);
        if (haveNext) {
            const int kn = (tile + 1) * 16;
            xa = *(const float4*)(Xp0 + kn);
            xb = *(const float4*)(Xp1 + kn);
            wa = *(const float4*)(Wp0 + kn);
            wb = *(const float4*)(Wp1 + kn);
        }
        const bool midflush = PANELS && (tile == 31);

#pragma unroll
        for (int k = 0; k < 16; ++k) {
            float4 a0 = *(const float4*)&Xs[buf][k][ty * 4];
            float4 a1 = *(const float4*)&Xs[buf][k][64 + ty * 4];
            float4 b0 = *(const float4*)&Ws[buf][k][tx * 4];
            float4 b1 = *(const float4*)&Ws[buf][k][64 + tx * 4];
            float av[8] = {a0.x, a0.y, a0.z, a0.w, a1.x, a1.y, a1.z, a1.w};
            float bv[8] = {b0.x, b0.y, b0.z, b0.w, b1.x, b1.y, b1.z, b1.w};
#pragma unroll
            for (int i = 0; i < 8; ++i)
#pragma unroll
                for (int j = 0; j < 8; ++j)
                    pan[i][j] = fmaf(av[i], bv[j], pan[i][j]);
            if (PANELS && k == 7 && midflush) {     // k = 504 boundary
#pragma unroll
                for (int i = 0; i < 8; ++i)
#pragma unroll
                    for (int j = 0; j < 8; ++j) {
                        acc[i][j] += pan[i][j];
                        pan[i][j] = 0.f;
                    }
            }
        }
        if (PANELS && (tile == 62 || tile == 63)) { // k = 1008, 1024
#pragma unroll
            for (int i = 0; i < 8; ++i)
#pragma unroll
                for (int j = 0; j < 8; ++j) {
                    acc[i][j] += pan[i][j];
                    pan[i][j] = 0.f;
                }
        }
        if (haveNext) {
            const int nb = buf ^ 1;
            Xs[nb][lc+0][lr] = xa.x; Xs[nb][lc+1][lr] = xa.y; Xs[nb][lc+2][lr] = xa.z; Xs[nb][lc+3][lr] = xa.w;
            Xs[nb][lc+0][lr+64] = xb.x; Xs[nb][lc+1][lr+64] = xb.y; Xs[nb][lc+2][lr+64] = xb.z; Xs[nb][lc+3][lr+64] = xb.w;
            Ws[nb][lc+0][lr] = wa.x; Ws[nb][lc+1][lr] = wa.y; Ws[nb][lc+2][lr] = wa.z; Ws[nb][lc+3][lr] = wa.w;
            Ws[nb][lc+0][lr+64] = wb.x; Ws[nb][lc+1][lr+64] = wb.y; Ws[nb][lc+2][lr+64] = wb.z; Ws[nb][lc+3][lr+64] = wb.w;
            __syncthreads();
            buf = nb;
        }
    }

#pragma unroll
    for (int i = 0; i < 8; ++i) {
        const int m = m0 + ((i < 4) ? (ty * 4 + i) : (64 + ty * 4 + i - 4));
#pragma unroll
        for (int j = 0; j < 8; ++j) {
            const int c = n0 + ((j < 4) ? (tx * 4 + j) : (64 + tx * 4 + j - 4));
            const float r = (PANELS ? acc[i][j] : pan[i][j]) + bias[c];
            if (MODE == 0) {
                Y[(size_t)m * Dc + c] = r;
            } else {
                const int bb = m >> 11;
                const int s  = m & (Sc - 1);
                const int hh = c >> 6;
                const int dk = c & 63;
                Y[(((size_t)(bb * Hc + hh) * Sc) + s) * DKc + dk] = r;
            }
        }
    }
}

// ---------------------------------------------------------------------------
// Attention v6: == v5 but staged K rows padded to 68 floats (272 B) and qs
// rows padded to 68 => the two half-warp K broadcasts hit disjoint banks
// (conflict-free LDS; 2x fewer K-read wavefronts). FP order unchanged.
// ---------------------------------------------------------------------------
#define TQ 16
#define SST 2052     // score row stride (floats)
#define NKT 128      // keys per staged tile (two 64-key halves)
#define KST 17       // staged K row stride in float4 (68 floats = 272 B)
#define QST 68       // q row stride (floats)
#define KSBUF4 (NKT * KST)   // one K buffer in float4 units

// Recompute submax over subgroup g (16 floats), ascending index, strict >.
#define SUBMAX(g, outm, outi)                                              \
    {                                                                      \
        float nv = -FLT_MAX; int ni = 0x7fffffff;                          \
        _Pragma("unroll")                                                  \
        for (int jj = 0; jj < 4; ++jj) {                                   \
            const int base = ((g) * 4 + jj) * 128 + lane * 4;              \
            const float4 vv = *(const float4*)&scr[base];                  \
            if (vv.x > nv) { nv = vv.x; ni = base; }                       \
            if (vv.y > nv) { nv = vv.y; ni = base + 1; }                   \
            if (vv.z > nv) { nv = vv.z; ni = base + 2; }                   \
            if (vv.w > nv) { nv = vv.w; ni = base + 3; }                   \
        }                                                                  \
        outm = mono(nv); outi = ni;                                        \
    }

// One 64-key half-tile of scores for this thread (keys jl, jl+1 of the half).
// kbase4: float4 index of key jl's row start within Ks.
#define SCORE_PAIR(kbase4, mm, jout)                                       \
    {                                                                      \
        const float4* k0p = (const float4*)Ks + (kbase4);                  \
        const float4* k1p = k0p + KST;                                     \
        float s0 = 0.f, s1 = 0.f;                                          \
        _Pragma("unroll")                                                  \
        for (int d = 0; d < 16; ++d) {                                     \
            float4 k0 = k0p[d];                                            \
            float4 k1 = k1p[d];                                            \
            s0 = fmaf(qv[d].x, k0.x, s0);                                  \
            s0 = fmaf(qv[d].y, k0.y, s0);                                  \
            s0 = fmaf(qv[d].z, k0.z, s0);                                  \
            s0 = fmaf(qv[d].w, k0.w, s0);                                  \
            s1 = fmaf(qv[d].x, k1.x, s1);                                  \
            s1 = fmaf(qv[d].y, k1.y, s1);                                  \
            s1 = fmaf(qv[d].z, k1.z, s1);                                  \
            s1 = fmaf(qv[d].w, k1.w, s1);                                  \
        }                                                                  \
        s0 *= 0.125f;                                                      \
        s1 *= 0.125f;                                                      \
        if ((mm).x == 0) s0 = -1e9f;                                       \
        if ((mm).y == 0) s1 = -1e9f;                                       \
        srow[(jout)]     = s0;                                             \
        srow[(jout) + 1] = s1;                                             \
    }

__global__ void __launch_bounds__(512, 1)
attn_v6(const int* __restrict__ mask, const int* __restrict__ topk_p)
{
    extern __shared__ float sm[];
    float* qs   = sm;                          // 16*68
    float* sc   = qs + TQ * QST;               // 16*2052
    float* Ks   = sc + TQ * SST;               // 2 * 128*68
    float* selv = Ks + 2 * NKT * KST * 4;      // 16*32
    float* sele = selv + TQ * KSEL;            // 16*32
    int*   seli = (int*)(sele + TQ * KSEL);    // 16*32

    const int tid = threadIdx.x;
    const int bh  = blockIdx.y;
    const int b   = bh >> 4;
    const int h   = bh & 15;
    const int q0  = blockIdx.x * TQ;

    const float* Qb = g_q + ((size_t)bh * Sc + q0) * DKc;
    const float* Kb = g_k + (size_t)bh * Sc * DKc;
    const float* Vb = g_v + (size_t)bh * Sc * DKc;

    // load Q tile (padded rows) + K tile 0 (padded rows)
    for (int i = tid; i < TQ * DKc; i += 512)
        qs[(i >> 6) * QST + (i & 63)] = Qb[i];
    {
        const float4* src = (const float4*)Kb;
        float4* dst = (float4*)Ks;
#pragma unroll
        for (int c = 0; c < 4; ++c) {
            const int idx = tid + c * 512;          // linear float4 index
            const int key = idx >> 4;
            const int dof = idx & 15;
            dst[key * KST + dof] = src[idx];
        }
    }
    __syncthreads();

    // ---- scores ----
    {
        const int r   = tid & 15;
        const int grp = tid >> 4;              // 0..31
        const int jl  = grp * 2;
        const int* mrow = mask + ((size_t)b * Sc + (q0 + r)) * Sc;
        float* srow = sc + r * SST;

        float4 qv[16];
#pragma unroll
        for (int d = 0; d < 16; ++d)
            qv[d] = *(const float4*)(qs + r * QST + d * 4);

        int buf = 0;
        for (int kt = 0; kt < Sc / NKT; ++kt) {
            const bool haveNext = (kt + 1 < Sc / NKT);
            const int jt = kt * NKT + jl;

            // hoisted mask loads for both halves
            const int2 mmA = *(const int2*)(mrow + jt);
            const int2 mmB = *(const int2*)(mrow + jt + 64);

            // prefetch first half of next tile
            float4 pf0, pf1;
            const float4* nsrc = (const float4*)(Kb + (size_t)(kt + 1) * NKT * DKc);
            if (haveNext) {
                pf0 = nsrc[tid];
                pf1 = nsrc[tid + 512];
            }

            // half 0
            SCORE_PAIR(buf * KSBUF4 + jl * KST, mmA, jt);

            float4 pf2, pf3;
            if (haveNext) {
                float4* dst = (float4*)Ks + (buf ^ 1) * KSBUF4;
                {
                    const int idx = tid;
                    dst[(idx >> 4) * KST + (idx & 15)] = pf0;
                }
                {
                    const int idx = tid + 512;
                    dst[(idx >> 4) * KST + (idx & 15)] = pf1;
                }
                pf2 = nsrc[tid + 1024];
                pf3 = nsrc[tid + 1536];
            }

            // half 1
            SCORE_PAIR(buf * KSBUF4 + (64 + jl) * KST, mmB, jt + 64);

            if (haveNext) {
                float4* dst = (float4*)Ks + (buf ^ 1) * KSBUF4;
                {
                    const int idx = tid + 1024;
                    dst[(idx >> 4) * KST + (idx & 15)] = pf2;
                }
                {
                    const int idx = tid + 1536;
                    dst[(idx >> 4) * KST + (idx & 15)] = pf3;
                }
                __syncthreads();
                buf ^= 1;
            }
        }
    }
    __syncthreads();

    int kk = *topk_p;
    if (kk > KSEL) kk = KSEL;

    // ---- top-k: warp w owns query row w (REDUX + cached sub-maxima) ----
    const int w    = tid >> 5;
    const int lane = tid & 31;
    float* scr = sc + w * SST;

    unsigned sm0, sm1, sm2, sm3;
    int      si0, si1, si2, si3;
    SUBMAX(0, sm0, si0);
    SUBMAX(1, sm1, si1);
    SUBMAX(2, sm2, si2);
    SUBMAX(3, sm3, si3);

    unsigned lvm; int li;
    {
        lvm = sm0; li = si0;
        if (sm1 > lvm) { lvm = sm1; li = si1; }
        if (sm2 > lvm) { lvm = sm2; li = si2; }
        if (sm3 > lvm) { lvm = sm3; li = si3; }
    }

    for (int sel = 0; sel < kk; ++sel) {
        const unsigned m = __reduce_max_sync(0xffffffffu, lvm);
        const int cand = (lvm == m) ? li : 0x7fffffff;
        const int mi = __reduce_min_sync(0xffffffffu, cand);

        if (lane == 0) {
            selv[w * KSEL + sel] = invmono(m);
            seli[w * KSEL + sel] = mi;
        }

        const int owner = (mi >> 2) & 31;
        if (lane == owner) {
            scr[mi] = -FLT_MAX;
            const int g = mi >> 9;
            switch (g) {
                case 0: SUBMAX(0, sm0, si0); break;
                case 1: SUBMAX(1, sm1, si1); break;
                case 2: SUBMAX(2, sm2, si2); break;
                default: SUBMAX(3, sm3, si3); break;
            }
            lvm = sm0; li = si0;
            if (sm1 > lvm) { lvm = sm1; li = si1; }
            if (sm2 > lvm) { lvm = sm2; li = si2; }
            if (sm3 > lvm) { lvm = sm3; li = si3; }
        }
    }

    // ---- softmax + ctx ----
    float* outp = g_ctx + ((size_t)(b * Sc + q0 + w)) * Dc + h * DKc;
    const float mx = selv[w * KSEL];             // first pick == row max

    if (kk == KSEL) {
        const float e = expf(selv[w * KSEL + lane] - mx);
        sele[w * KSEL + lane] = e;
        __syncwarp();
        float ssum = 0.f;
#pragma unroll
        for (int i = 0; i < KSEL; ++i)           // strictly ascending
            ssum += sele[w * KSEL + i];
        const float p = e / ssum;

        const int myi = seli[w * KSEL + lane];
        float a0 = 0.f, a1 = 0.f;
#pragma unroll
        for (int sel = 0; sel < KSEL; ++sel) {   // ascending: bit-exact
            const float pp = __shfl_sync(0xffffffffu, p, sel);
            const int   id = __shfl_sync(0xffffffffu, myi, sel);
            const float* vp = Vb + (size_t)id * DKc;
            a0 = fmaf(pp, vp[lane],      a0);
            a1 = fmaf(pp, vp[lane + 32], a1);
        }
        outp[lane]      = a0;
        outp[lane + 32] = a1;
    } else {
        float e = 0.f;
        if (lane < kk) {
            e = expf(selv[w * KSEL + lane] - mx);
            sele[w * KSEL + lane] = e;
        }
        __syncwarp();
        float ssum = 0.f;
        for (int i = 0; i < kk; ++i)
            ssum += sele[w * KSEL + i];
        const float p = e / ssum;

        const int myi = (lane < kk) ? seli[w * KSEL + lane] : 0;
        float a0 = 0.f, a1 = 0.f;
        for (int sel = 0; sel < kk; ++sel) {
            const float pp = __shfl_sync(0xffffffffu, p, sel);
            const int   id = __shfl_sync(0xffffffffu, myi, sel);
            const float* vp = Vb + (size_t)id * DKc;
            a0 = fmaf(pp, vp[lane],      a0);
            a1 = fmaf(pp, vp[lane + 32], a1);
        }
        outp[lane]      = a0;
        outp[lane + 32] = a1;
    }
}

#define SMEM_ATTN ((TQ*QST + TQ*SST + 2*NKT*KST*4 + TQ*KSEL*2) * 4 + TQ*KSEL * 4)

// ---------------------------------------------------------------------------
extern "C" void kernel_launch(void* const* d_in, const int* in_sizes, int n_in,
                              void* d_out, int out_size)
{
    const float* query = (const float*)d_in[0];
    const float* key   = (const float*)d_in[1];
    const float* value = (const float*)d_in[2];
    const float* Wq    = (const float*)d_in[3];
    const float* bq    = (const float*)d_in[4];
    const float* Wk    = (const float*)d_in[5];
    const float* bk    = (const float*)d_in[6];
    const float* Wv    = (const float*)d_in[7];
    const float* bv    = (const float*)d_in[8];
    const float* Wo    = (const float*)d_in[9];
    const float* bo    = (const float*)d_in[10];
    const int*   mask  = (const int*)d_in[11];
    const int*   topk  = (const int*)d_in[12];
    float* out = (float*)d_out;

    float *pq, *pk, *pv, *pctx;
    cudaGetSymbolAddress((void**)&pq,   g_q);
    cudaGetSymbolAddress((void**)&pk,   g_k);
    cudaGetSymbolAddress((void**)&pv,   g_v);
    cudaGetSymbolAddress((void**)&pctx, g_ctx);

    cudaFuncSetAttribute(attn_v6,
                         cudaFuncAttributeMaxDynamicSharedMemorySize, SMEM_ATTN);

    dim3 gg(Dc / 128, (Bc * Sc) / 128);   // (8, 32)

    // Q, K: bit-exact Eigen panel accumulation
    gemm_v2<1, 1><<<gg, 256>>>(query, Wq, bq, pq);
    gemm_v2<1, 1><<<gg, 256>>>(key,   Wk, bk, pk);
    // V: linear path — single-chain accumulator
    gemm_v2<1, 0><<<gg, 256>>>(value, Wv, bv, pv);

    attn_v6<<<dim3(Sc / TQ, Bc * Hc), 512, SMEM_ATTN>>>(mask, topk);

    // output projection: linear path
    gemm_v2<0, 0><<<gg, 256>>>(pctx, Wo, bo, out);
}